// round 16
// baseline (speedup 1.0000x reference)
#include <cuda_runtime.h>
#include <math.h>
#include <stdint.h>

#define IN_DIM 1024
#define ED 256
#define NE 512
#define NTOK_MAX 131072
#define TT 32
#define XTP 68
#define PSTP 36
#define BK1 32
#define BK2 16
#define LEAD 296

typedef unsigned long long u64;
typedef uint32_t u32;

__device__ __align__(16) float g_WT[IN_DIM * ED];     // W transposed [k][n]
__device__ __align__(16) float g_cnT[ED * NE];        // normalized centers [k][e]
__device__ __align__(16) float g_P[(size_t)NTOK_MAX * ED];
__device__ float g_sq[NTOK_MAX];
__device__ u32 g_flag[NTOK_MAX / 64];

static __device__ __forceinline__ u64 pack2(float lo, float hi) {
    u64 r; asm("mov.b64 %0, {%1, %2};" : "=l"(r) : "f"(lo), "f"(hi)); return r;
}
static __device__ __forceinline__ void unpack2(u64 v, float& lo, float& hi) {
    asm("mov.b64 {%0, %1}, %2;" : "=f"(lo), "=f"(hi) : "l"(v));
}
static __device__ __forceinline__ void ffma2(u64& d, u64 a, u64 b) {
    asm("fma.rn.f32x2 %0, %1, %2, %0;" : "+l"(d) : "l"(a), "l"(b));
}
static __device__ __forceinline__ void fadd2(u64& d, u64 a) {
    asm("add.rn.f32x2 %0, %0, %1;" : "+l"(d) : "l"(a));
}

// ---- bulk async copy + mbarrier helpers ----
static __device__ __forceinline__ void mbar_init(u32 mbar, u32 cnt) {
    asm volatile("mbarrier.init.shared.b64 [%0], %1;" :: "r"(mbar), "r"(cnt) : "memory");
}
static __device__ __forceinline__ void mbar_expect_tx(u32 mbar, u32 bytes) {
    asm volatile("mbarrier.arrive.expect_tx.shared.b64 _, [%0], %1;" :: "r"(mbar), "r"(bytes) : "memory");
}
static __device__ __forceinline__ void bulk_g2s(u32 dst, const float* src,
                                                u32 bytes, u32 mbar) {
    asm volatile("cp.async.bulk.shared::cta.global.mbarrier::complete_tx::bytes [%0], [%1], %2, [%3];"
                 :: "r"(dst), "l"(src), "r"(bytes), "r"(mbar) : "memory");
}
static __device__ __forceinline__ void mbar_wait(u32 mbar, u32 parity) {
    u32 done;
    asm volatile(
        "{\n\t.reg .pred p;\n\t"
        "mbarrier.try_wait.parity.acquire.cta.shared::cta.b64 p, [%1], %2;\n\t"
        "selp.b32 %0, 1, 0, p;\n\t}"
        : "=r"(done) : "r"(mbar), "r"(parity) : "memory");
    if (!done) {
        asm volatile(
            "{\n\t.reg .pred P1;\n\t"
            "WL_%=:\n\t"
            "mbarrier.try_wait.parity.acquire.cta.shared::cta.b64 P1, [%0], %1, 0x989680;\n\t"
            "@P1 bra.uni WD_%=;\n\t"
            "bra.uni WL_%=;\n\t"
            "WD_%=:\n\t}"
            :: "r"(mbar), "r"(parity) : "memory");
    }
}

static __device__ __forceinline__ void upd(float v, int i,
                                           float& v1, int& i1, float& v2, int& i2) {
    if (v > v1 || (v == v1 && i < i1)) { v2 = v1; i2 = i1; v1 = v; i1 = i; }
    else if (v > v2 || (v == v2 && i < i2)) { v2 = v; i2 = i; }
}

// ---------------- prep (fused): normalize centers + transpose W + zero flags ----------------
__global__ void prep_kernel(const float* __restrict__ centers, const float* __restrict__ W) {
    __shared__ float tsh[32][33];
    __shared__ float ws[8];
    int bid = blockIdx.x, tid = threadIdx.x;
    if (bid < 8) g_flag[bid * 256 + tid] = 0;
    if (bid < NE) {
        int e = bid, t = tid;
        float v = centers[e * ED + t];
        float s = v * v;
        #pragma unroll
        for (int o = 16; o; o >>= 1) s += __shfl_xor_sync(0xffffffffu, s, o);
        if ((t & 31) == 0) ws[t >> 5] = s;
        __syncthreads();
        float tot = 0.f;
        #pragma unroll
        for (int i = 0; i < 8; ++i) tot += ws[i];
        float norm = fmaxf(sqrtf(tot), 1e-12f);
        g_cnT[t * NE + e] = v / norm;
    } else {
        int b = bid - NE;
        int bx = (b & 31) * 32;            // k block (IN_DIM/32 = 32)
        int by = (b >> 5) * 32;            // n block (ED/32 = 8)
        int x = tid & 31, y = tid >> 5;    // 32 x 8
        #pragma unroll
        for (int j = 0; j < 32; j += 8)
            tsh[y + j][x] = W[(size_t)(by + y + j) * IN_DIM + bx + x];
        __syncthreads();
        #pragma unroll
        for (int j = 0; j < 32; j += 8)
            g_WT[(size_t)(bx + y + j) * ED + by + x] = tsh[x][y + j];
    }
}

// ---------------- fused main kernel: role 0 = GEMM1 CTA, role 1 = router CTA ----------------
#define W1BYTES (BK1 * ED * 4)
#define C2BYTES (BK2 * NE * 4)
#define MGP 129

__global__ __launch_bounds__(256, 2)
void main_kernel(const float* __restrict__ x, const float* __restrict__ bias,
                 float* __restrict__ out, int ntok) {
    extern __shared__ __align__(16) float sm[];
    __shared__ __align__(8) u64 mbars[2];
    __shared__ float sq_sm[64][2];

    const int tid = threadIdx.x;
    const int w = tid >> 5, lane = tid & 31;
    const int NK1 = ntok / 64;

    // bid -> (role, idx): LEAD pure k1 bids, then 1 k1 : 2 k2 interleave, then leftover k2
    int bid = blockIdx.x;
    int role, idx;
    if (bid < LEAD) { role = 0; idx = bid; }
    else {
        int r = bid - LEAD, gq = r / 3, m = r - 3 * gq;
        if (gq < NK1 - LEAD) {
            if (m == 0) { role = 0; idx = LEAD + gq; }
            else        { role = 1; idx = 2 * gq + m - 1; }
        } else {
            role = 1; idx = 2 * (NK1 - LEAD) + (bid - (LEAD + 3 * (NK1 - LEAD)));
        }
    }

    u32 mb0 = (u32)__cvta_generic_to_shared(&mbars[0]);
    u32 mb1 = mb0 + 8;
    int ph0 = 0, ph1 = 0;

    if (role == 0) {
        // ================= GEMM1: P = x @ W^T + b =================
        float* xT = sm;                        // [2][BK1][XTP]
        float* wS = sm + 2 * BK1 * XTP;        // [2][BK1][ED]
        const int t0 = idx * 64;
        const int mb = (w & 3) * 16;
        const int nc = (w >> 2) * 128 + lane * 4;

        const int xr = tid >> 2, xk = (tid & 3) * 8;
        const float* xp = x + (size_t)(t0 + xr) * IN_DIM + xk;
        u32 wS_u32 = (u32)__cvta_generic_to_shared(wS);

        u64 acc[8][4];
        #pragma unroll
        for (int m2 = 0; m2 < 8; ++m2)
            #pragma unroll
            for (int p = 0; p < 4; ++p) acc[m2][p] = 0ull;

        if (tid == 0) { mbar_init(mb0, 1); mbar_init(mb1, 1); }
        __syncthreads();

        if (tid == 0) { mbar_expect_tx(mb0, W1BYTES); bulk_g2s(wS_u32, g_WT, W1BYTES, mb0); }
        float4 xs0 = *(const float4*)xp;
        float4 xs1 = *(const float4*)(xp + 4);
        {
            float v[8] = {xs0.x, xs0.y, xs0.z, xs0.w, xs1.x, xs1.y, xs1.z, xs1.w};
            #pragma unroll
            for (int i = 0; i < 8; ++i)
                xT[(xk + i) * XTP + xr] = v[i];
        }
        mbar_wait(mb0, ph0); ph0 ^= 1;
        __syncthreads();

        const int NT = IN_DIM / BK1;
        for (int kt = 0; kt < NT; ++kt) {
            const int buf = kt & 1;
            const float* xb = xT + buf * (BK1 * XTP);
            const float* wb = wS + buf * (BK1 * ED);
            if (kt + 1 < NT) {
                if (tid == 0) {
                    u32 m = buf ? mb0 : mb1;
                    mbar_expect_tx(m, W1BYTES);
                    bulk_g2s(wS_u32 + (u32)((buf ^ 1) * W1BYTES),
                             g_WT + (size_t)(kt + 1) * BK1 * ED, W1BYTES, m);
                }
                xs0 = *(const float4*)(xp + (kt + 1) * BK1);
                xs1 = *(const float4*)(xp + (kt + 1) * BK1 + 4);
            }
            #pragma unroll
            for (int k = 0; k < BK1; ++k) {
                const ulonglong2* ap = (const ulonglong2*)(xb + k * XTP + mb);
                ulonglong2 qa0 = ap[0], qa1 = ap[1], qa2 = ap[2], qa3 = ap[3];
                float4 b = *(const float4*)(wb + k * ED + nc);
                u64 B0 = pack2(b.x, b.x), B1 = pack2(b.y, b.y);
                u64 B2 = pack2(b.z, b.z), B3 = pack2(b.w, b.w);
                ffma2(acc[0][0], qa0.x, B0); ffma2(acc[0][1], qa0.x, B1);
                ffma2(acc[0][2], qa0.x, B2); ffma2(acc[0][3], qa0.x, B3);
                ffma2(acc[1][0], qa0.y, B0); ffma2(acc[1][1], qa0.y, B1);
                ffma2(acc[1][2], qa0.y, B2); ffma2(acc[1][3], qa0.y, B3);
                ffma2(acc[2][0], qa1.x, B0); ffma2(acc[2][1], qa1.x, B1);
                ffma2(acc[2][2], qa1.x, B2); ffma2(acc[2][3], qa1.x, B3);
                ffma2(acc[3][0], qa1.y, B0); ffma2(acc[3][1], qa1.y, B1);
                ffma2(acc[3][2], qa1.y, B2); ffma2(acc[3][3], qa1.y, B3);
                ffma2(acc[4][0], qa2.x, B0); ffma2(acc[4][1], qa2.x, B1);
                ffma2(acc[4][2], qa2.x, B2); ffma2(acc[4][3], qa2.x, B3);
                ffma2(acc[5][0], qa2.y, B0); ffma2(acc[5][1], qa2.y, B1);
                ffma2(acc[5][2], qa2.y, B2); ffma2(acc[5][3], qa2.y, B3);
                ffma2(acc[6][0], qa3.x, B0); ffma2(acc[6][1], qa3.x, B1);
                ffma2(acc[6][2], qa3.x, B2); ffma2(acc[6][3], qa3.x, B3);
                ffma2(acc[7][0], qa3.y, B0); ffma2(acc[7][1], qa3.y, B1);
                ffma2(acc[7][2], qa3.y, B2); ffma2(acc[7][3], qa3.y, B3);
            }
            if (kt + 1 < NT) {
                float* xn = xT + (buf ^ 1) * (BK1 * XTP);
                float v[8] = {xs0.x, xs0.y, xs0.z, xs0.w, xs1.x, xs1.y, xs1.z, xs1.w};
                #pragma unroll
                for (int i = 0; i < 8; ++i)
                    xn[(xk + i) * XTP + xr] = v[i];
                if (buf) { mbar_wait(mb0, ph0); ph0 ^= 1; }
                else     { mbar_wait(mb1, ph1); ph1 ^= 1; }
            }
            __syncthreads();
        }

        // epilogue: +bias, sumsq butterfly, store P + g_sq, release flag
        float4 b4 = *(const float4*)(bias + nc);
        u64 bp[4];
        bp[0] = pack2(b4.x, b4.x); bp[1] = pack2(b4.y, b4.y);
        bp[2] = pack2(b4.z, b4.z); bp[3] = pack2(b4.w, b4.w);

        u64 sp[8];
        #pragma unroll
        for (int m2 = 0; m2 < 8; ++m2) {
            sp[m2] = 0ull;
            #pragma unroll
            for (int j = 0; j < 4; ++j) {
                fadd2(acc[m2][j], bp[j]);
                ffma2(sp[m2], acc[m2][j], acc[m2][j]);
            }
        }
        #pragma unroll
        for (int m2 = 0; m2 < 8; ++m2)
            #pragma unroll
            for (int o = 16; o; o >>= 1) {
                u64 t = __shfl_xor_sync(0xffffffffu, sp[m2], o);
                fadd2(sp[m2], t);
            }

        #pragma unroll
        for (int m2 = 0; m2 < 8; ++m2) {
            float lo[4], hi[4];
            #pragma unroll
            for (int j = 0; j < 4; ++j) unpack2(acc[m2][j], lo[j], hi[j]);
            int r = t0 + mb + 2 * m2;
            *(float4*)(g_P + (size_t)r * ED + nc)       = make_float4(lo[0], lo[1], lo[2], lo[3]);
            *(float4*)(g_P + (size_t)(r + 1) * ED + nc) = make_float4(hi[0], hi[1], hi[2], hi[3]);
        }
        if (lane == 0) {
            #pragma unroll
            for (int m2 = 0; m2 < 8; ++m2) {
                float se, so; unpack2(sp[m2], se, so);
                sq_sm[mb + 2 * m2][w >> 2]     = se;
                sq_sm[mb + 2 * m2 + 1][w >> 2] = so;
            }
        }
        __syncthreads();
        if (tid < 64) g_sq[t0 + tid] = sq_sm[tid][0] + sq_sm[tid][1];
        __syncthreads();
        if (tid == 0) {
            __threadfence();
            asm volatile("st.release.gpu.global.b32 [%0], %1;"
                         :: "l"(g_flag + idx), "r"(1u) : "memory");
        }
    } else {
        // ================= router: sims + top-2 + softmax =================
        float* PsT = sm;                       // [ED][PSTP]
        float* ct  = sm + ED * PSTP;           // [2][BK2][NE]
        const int t0 = idx * TT;
        const int g = w >> 2, h = w & 3;
        const int mb = g * 16;
        const int nc = h * 128 + lane * 4;
        u32 ct_u32 = (u32)__cvta_generic_to_shared(ct);

        if (tid == 0) { mbar_init(mb0, 1); mbar_init(mb1, 1); }
        __syncthreads();
        if (tid == 0) {
            mbar_expect_tx(mb0, C2BYTES); bulk_g2s(ct_u32, g_cnT, C2BYTES, mb0);
            // acquire-spin on producer's flag (overlapped with ct bulk copy)
            u32 f;
            do {
                asm volatile("ld.acquire.gpu.global.b32 %0, [%1];"
                             : "=r"(f) : "l"(g_flag + (idx >> 1)) : "memory");
                if (!f) asm volatile("nanosleep.u32 256;");
            } while (!f);
        }
        __syncthreads();   // publishes P visibility (acquire by tid0 + barrier)

        // transpose P tile into PsT (overlaps with bulk copy)
        const int pr = tid >> 3, pcq = (tid & 7) * 4;
        #pragma unroll
        for (int j = 0; j < 8; ++j) {
            int c = pcq + 32 * j;
            float4 v = *(const float4*)(g_P + (size_t)(t0 + pr) * ED + c);
            PsT[(c + 0) * PSTP + pr] = v.x;
            PsT[(c + 1) * PSTP + pr] = v.y;
            PsT[(c + 2) * PSTP + pr] = v.z;
            PsT[(c + 3) * PSTP + pr] = v.w;
        }
        mbar_wait(mb0, ph0); ph0 ^= 1;
        __syncthreads();

        u64 acc[8][4];
        #pragma unroll
        for (int m2 = 0; m2 < 8; ++m2)
            #pragma unroll
            for (int p = 0; p < 4; ++p) acc[m2][p] = 0ull;

        const int NT = ED / BK2;
        for (int kt = 0; kt < NT; ++kt) {
            const int buf = kt & 1;
            const float* cb = ct + buf * (BK2 * NE);
            if (kt + 1 < NT && tid == 0) {
                u32 m = buf ? mb0 : mb1;
                mbar_expect_tx(m, C2BYTES);
                bulk_g2s(ct_u32 + (u32)((buf ^ 1) * C2BYTES),
                         g_cnT + (size_t)(kt + 1) * BK2 * NE, C2BYTES, m);
            }
            #pragma unroll
            for (int k = 0; k < BK2; ++k) {
                const int kk = kt * BK2 + k;
                const ulonglong2* ap = (const ulonglong2*)(PsT + kk * PSTP + mb);
                ulonglong2 qa0 = ap[0], qa1 = ap[1], qa2 = ap[2], qa3 = ap[3];
                float4 b = *(const float4*)(cb + k * NE + nc);
                u64 B0 = pack2(b.x, b.x), B1 = pack2(b.y, b.y);
                u64 B2 = pack2(b.z, b.z), B3 = pack2(b.w, b.w);
                ffma2(acc[0][0], qa0.x, B0); ffma2(acc[0][1], qa0.x, B1);
                ffma2(acc[0][2], qa0.x, B2); ffma2(acc[0][3], qa0.x, B3);
                ffma2(acc[1][0], qa0.y, B0); ffma2(acc[1][1], qa0.y, B1);
                ffma2(acc[1][2], qa0.y, B2); ffma2(acc[1][3], qa0.y, B3);
                ffma2(acc[2][0], qa1.x, B0); ffma2(acc[2][1], qa1.x, B1);
                ffma2(acc[2][2], qa1.x, B2); ffma2(acc[2][3], qa1.x, B3);
                ffma2(acc[3][0], qa1.y, B0); ffma2(acc[3][1], qa1.y, B1);
                ffma2(acc[3][2], qa1.y, B2); ffma2(acc[3][3], qa1.y, B3);
                ffma2(acc[4][0], qa2.x, B0); ffma2(acc[4][1], qa2.x, B1);
                ffma2(acc[4][2], qa2.x, B2); ffma2(acc[4][3], qa2.x, B3);
                ffma2(acc[5][0], qa2.y, B0); ffma2(acc[5][1], qa2.y, B1);
                ffma2(acc[5][2], qa2.y, B2); ffma2(acc[5][3], qa2.y, B3);
                ffma2(acc[6][0], qa3.x, B0); ffma2(acc[6][1], qa3.x, B1);
                ffma2(acc[6][2], qa3.x, B2); ffma2(acc[6][3], qa3.x, B3);
                ffma2(acc[7][0], qa3.y, B0); ffma2(acc[7][1], qa3.y, B1);
                ffma2(acc[7][2], qa3.y, B2); ffma2(acc[7][3], qa3.y, B3);
            }
            if (kt + 1 < NT) {
                if (buf) { mbar_wait(mb0, ph0); ph0 ^= 1; }
                else     { mbar_wait(mb1, ph1); ph1 ^= 1; }
            }
            __syncthreads();
        }

        // per-thread top-2 over this thread's 4 experts, per token slot
        float v1[16], v2[16]; int i1[16], i2[16];
        #pragma unroll
        for (int s = 0; s < 16; ++s) { v1[s] = -INFINITY; v2[s] = -INFINITY; i1[s] = 0; i2[s] = 0; }
        #pragma unroll
        for (int m2 = 0; m2 < 8; ++m2)
            #pragma unroll
            for (int j = 0; j < 4; ++j) {
                float lo, hi; unpack2(acc[m2][j], lo, hi);
                int gi = nc + j;
                upd(lo, gi, v1[2 * m2],     i1[2 * m2],     v2[2 * m2],     i2[2 * m2]);
                upd(hi, gi, v1[2 * m2 + 1], i1[2 * m2 + 1], v2[2 * m2 + 1], i2[2 * m2 + 1]);
            }

        // write per-lane top2 to mg (overlaid on all of sm; PsT+ct dead after last sync)
        float4* mg = (float4*)sm;              // [TT][MGP] ; entry = h*32 + lane
        #pragma unroll
        for (int s = 0; s < 16; ++s)
            mg[(mb + s) * MGP + h * 32 + lane] =
                make_float4(v1[s], __int_as_float(i1[s]), v2[s], __int_as_float(i2[s]));
        __syncthreads();

        // merge: 128 threads, (token, quarter); scan 32 entries, shfl merge over 4 quarters
        if (tid < 128) {
            const int token = tid >> 2, q = tid & 3;
            const float4* row = mg + token * MGP + q * 32;
            float4 E = row[0];
            float V1 = E.x, V2 = E.z;
            int I1 = __float_as_int(E.y), I2 = __float_as_int(E.w);
            #pragma unroll 8
            for (int e = 1; e < 32; ++e) {
                E = row[e];
                upd(E.x, __float_as_int(E.y), V1, I1, V2, I2);
                upd(E.z, __float_as_int(E.w), V1, I1, V2, I2);
            }
            #pragma unroll
            for (int off = 1; off <= 2; off <<= 1) {
                float o1 = __shfl_xor_sync(0xffffffffu, V1, off);
                int  oi1 = __shfl_xor_sync(0xffffffffu, I1, off);
                float o2 = __shfl_xor_sync(0xffffffffu, V2, off);
                int  oi2 = __shfl_xor_sync(0xffffffffu, I2, off);
                upd(o1, oi1, V1, I1, V2, I2);
                upd(o2, oi2, V1, I1, V2, I2);
            }
            if (q == 0) {
                int tok = t0 + token;
                float inv = 1.f / fmaxf(sqrtf(g_sq[tok]), 1e-12f);
                float e2 = expf((V2 - V1) * inv);
                float den = 1.f + e2;
                out[2 * tok]     = 1.f / den;
                out[2 * tok + 1] = e2 / den;
                float* oi = out + 2 * (size_t)ntok;
                oi[2 * tok]     = (float)I1;
                oi[2 * tok + 1] = (float)I2;
            }
        }
    }
}

extern "C" void kernel_launch(void* const* d_in, const int* in_sizes, int n_in,
                              void* d_out, int out_size) {
    const float* x = (const float*)d_in[0];
    const float* W = (const float*)d_in[1];
    const float* b = (const float*)d_in[2];
    const float* c = (const float*)d_in[3];
    int ntok = in_sizes[0] / IN_DIM;   // 131072

    prep_kernel<<<NE + (IN_DIM / 32) * (ED / 32), 256>>>(c, W);

    int smem = (ED * PSTP + 2 * BK2 * NE) * (int)sizeof(float);        // 102400 B (>= k1's 82944)
    cudaFuncSetAttribute(main_kernel, cudaFuncAttributeMaxDynamicSharedMemorySize, smem);
    int grid = ntok / 64 + ntok / TT;                                  // 2048 + 4096 = 6144
    main_kernel<<<grid, 256, smem>>>(x, b, (float*)d_out, ntok);
}

// round 17
// speedup vs baseline: 1.0203x; 1.0203x over previous
#include <cuda_runtime.h>
#include <math.h>
#include <stdint.h>

#define IN_DIM 1024
#define ED 256
#define NE 512
#define NTOK_MAX 131072
#define TT 32
#define XTP 68
#define PSTP 36
#define BK1 32
#define BK2 16

typedef unsigned long long u64;
typedef uint32_t u32;

__device__ __align__(16) float g_WT[IN_DIM * ED];     // W transposed [k][n]
__device__ __align__(16) float g_cnT[ED * NE];        // normalized centers [k][e]
__device__ __align__(16) float g_P[(size_t)NTOK_MAX * ED];
__device__ float g_sq[NTOK_MAX];

static __device__ __forceinline__ u64 pack2(float lo, float hi) {
    u64 r; asm("mov.b64 %0, {%1, %2};" : "=l"(r) : "f"(lo), "f"(hi)); return r;
}
static __device__ __forceinline__ void unpack2(u64 v, float& lo, float& hi) {
    asm("mov.b64 {%0, %1}, %2;" : "=f"(lo), "=f"(hi) : "l"(v));
}
static __device__ __forceinline__ void ffma2(u64& d, u64 a, u64 b) {
    asm("fma.rn.f32x2 %0, %1, %2, %0;" : "+l"(d) : "l"(a), "l"(b));
}
static __device__ __forceinline__ void fadd2(u64& d, u64 a) {
    asm("add.rn.f32x2 %0, %0, %1;" : "+l"(d) : "l"(a));
}

// ---- bulk async copy + mbarrier helpers ----
static __device__ __forceinline__ void mbar_init(u32 mbar, u32 cnt) {
    asm volatile("mbarrier.init.shared.b64 [%0], %1;" :: "r"(mbar), "r"(cnt) : "memory");
}
static __device__ __forceinline__ void mbar_expect_tx(u32 mbar, u32 bytes) {
    asm volatile("mbarrier.arrive.expect_tx.shared.b64 _, [%0], %1;" :: "r"(mbar), "r"(bytes) : "memory");
}
static __device__ __forceinline__ void bulk_g2s(u32 dst, const float* src,
                                                u32 bytes, u32 mbar) {
    asm volatile("cp.async.bulk.shared::cta.global.mbarrier::complete_tx::bytes [%0], [%1], %2, [%3];"
                 :: "r"(dst), "l"(src), "r"(bytes), "r"(mbar) : "memory");
}
static __device__ __forceinline__ void mbar_wait(u32 mbar, u32 parity) {
    u32 done;
    asm volatile(
        "{\n\t.reg .pred p;\n\t"
        "mbarrier.try_wait.parity.acquire.cta.shared::cta.b64 p, [%1], %2;\n\t"
        "selp.b32 %0, 1, 0, p;\n\t}"
        : "=r"(done) : "r"(mbar), "r"(parity) : "memory");
    if (!done) {
        asm volatile(
            "{\n\t.reg .pred P1;\n\t"
            "WL_%=:\n\t"
            "mbarrier.try_wait.parity.acquire.cta.shared::cta.b64 P1, [%0], %1, 0x989680;\n\t"
            "@P1 bra.uni WD_%=;\n\t"
            "bra.uni WL_%=;\n\t"
            "WD_%=:\n\t}"
            :: "r"(mbar), "r"(parity) : "memory");
    }
}

static __device__ __forceinline__ void upd(float v, int i,
                                           float& v1, int& i1, float& v2, int& i2) {
    if (v > v1 || (v == v1 && i < i1)) { v2 = v1; i2 = i1; v1 = v; i1 = i; }
    else if (v > v2 || (v == v2 && i < i2)) { v2 = v; i2 = i; }
}

// ---------------- prep (fused): normalize centers + transpose W ----------------
__global__ void prep_kernel(const float* __restrict__ centers, const float* __restrict__ W) {
    __shared__ float tsh[32][33];
    __shared__ float ws[8];
    int bid = blockIdx.x, tid = threadIdx.x;
    if (bid < NE) {
        int e = bid, t = tid;
        float v = centers[e * ED + t];
        float s = v * v;
        #pragma unroll
        for (int o = 16; o; o >>= 1) s += __shfl_xor_sync(0xffffffffu, s, o);
        if ((t & 31) == 0) ws[t >> 5] = s;
        __syncthreads();
        float tot = 0.f;
        #pragma unroll
        for (int i = 0; i < 8; ++i) tot += ws[i];
        float norm = fmaxf(sqrtf(tot), 1e-12f);
        g_cnT[t * NE + e] = v / norm;
    } else {
        int b = bid - NE;
        int bx = (b & 31) * 32;            // k block (IN_DIM/32 = 32)
        int by = (b >> 5) * 32;            // n block (ED/32 = 8)
        int x = tid & 31, y = tid >> 5;    // 32 x 8
        #pragma unroll
        for (int j = 0; j < 32; j += 8)
            tsh[y + j][x] = W[(size_t)(by + y + j) * IN_DIM + bx + x];
        __syncthreads();
        #pragma unroll
        for (int j = 0; j < 32; j += 8)
            g_WT[(size_t)(bx + y + j) * ED + by + x] = tsh[x][y + j];
    }
}

// ---------------- K1: P = x @ W^T + b  (16m x 4n per thread, m-pair accs) ----------------
#define W1BYTES (BK1 * ED * 4)

__global__ __launch_bounds__(256, 2)
void k1_kernel(const float* __restrict__ x, const float* __restrict__ bias) {
    extern __shared__ __align__(16) float sm1[];
    float* xT = sm1;                       // [2][BK1][XTP]  x transposed (non-dup), k-major
    float* wS = sm1 + 2 * BK1 * XTP;       // [2][BK1][ED]   W tile, k-major
    __shared__ __align__(8) u64 mbars[2];
    __shared__ float sq_sm[64][2];

    const int tid = threadIdx.x;
    const int w = tid >> 5, lane = tid & 31;
    const int t0 = blockIdx.x * 64;
    const int mb = (w & 3) * 16;           // 16 rows per warp
    const int nc = (w >> 2) * 128 + lane * 4;  // 4 cols per lane, 128-col half per warp group

    const int xr = tid >> 2, xk = (tid & 3) * 8;
    const float* xp = x + (size_t)(t0 + xr) * IN_DIM + xk;

    u32 wS_u32 = (u32)__cvta_generic_to_shared(wS);
    u32 mb0 = (u32)__cvta_generic_to_shared(&mbars[0]);
    u32 mb1 = mb0 + 8;
    int ph0 = 0, ph1 = 0;

    u64 acc[8][4];
    #pragma unroll
    for (int m = 0; m < 8; ++m)
        #pragma unroll
        for (int p = 0; p < 4; ++p) acc[m][p] = 0ull;

    if (tid == 0) { mbar_init(mb0, 1); mbar_init(mb1, 1); }
    __syncthreads();

    if (tid == 0) { mbar_expect_tx(mb0, W1BYTES); bulk_g2s(wS_u32, g_WT, W1BYTES, mb0); }
    float4 xs0 = *(const float4*)xp;
    float4 xs1 = *(const float4*)(xp + 4);
    {
        float v[8] = {xs0.x, xs0.y, xs0.z, xs0.w, xs1.x, xs1.y, xs1.z, xs1.w};
        #pragma unroll
        for (int i = 0; i < 8; ++i)
            xT[(xk + i) * XTP + xr] = v[i];
    }
    mbar_wait(mb0, ph0); ph0 ^= 1;
    __syncthreads();

    const int NT = IN_DIM / BK1;
    for (int kt = 0; kt < NT; ++kt) {
        const int buf = kt & 1;
        const float* xb = xT + buf * (BK1 * XTP);
        const float* wb = wS + buf * (BK1 * ED);
        if (kt + 1 < NT) {
            if (tid == 0) {
                u32 m = buf ? mb0 : mb1;
                mbar_expect_tx(m, W1BYTES);
                bulk_g2s(wS_u32 + (u32)((buf ^ 1) * W1BYTES),
                         g_WT + (size_t)(kt + 1) * BK1 * ED, W1BYTES, m);
            }
            xs0 = *(const float4*)(xp + (kt + 1) * BK1);
            xs1 = *(const float4*)(xp + (kt + 1) * BK1 + 4);
        }
        #pragma unroll
        for (int k = 0; k < BK1; ++k) {
            const ulonglong2* ap = (const ulonglong2*)(xb + k * XTP + mb);
            ulonglong2 qa0 = ap[0], qa1 = ap[1], qa2 = ap[2], qa3 = ap[3];
            float4 b = *(const float4*)(wb + k * ED + nc);
            u64 B0 = pack2(b.x, b.x), B1 = pack2(b.y, b.y);
            u64 B2 = pack2(b.z, b.z), B3 = pack2(b.w, b.w);
            ffma2(acc[0][0], qa0.x, B0); ffma2(acc[0][1], qa0.x, B1);
            ffma2(acc[0][2], qa0.x, B2); ffma2(acc[0][3], qa0.x, B3);
            ffma2(acc[1][0], qa0.y, B0); ffma2(acc[1][1], qa0.y, B1);
            ffma2(acc[1][2], qa0.y, B2); ffma2(acc[1][3], qa0.y, B3);
            ffma2(acc[2][0], qa1.x, B0); ffma2(acc[2][1], qa1.x, B1);
            ffma2(acc[2][2], qa1.x, B2); ffma2(acc[2][3], qa1.x, B3);
            ffma2(acc[3][0], qa1.y, B0); ffma2(acc[3][1], qa1.y, B1);
            ffma2(acc[3][2], qa1.y, B2); ffma2(acc[3][3], qa1.y, B3);
            ffma2(acc[4][0], qa2.x, B0); ffma2(acc[4][1], qa2.x, B1);
            ffma2(acc[4][2], qa2.x, B2); ffma2(acc[4][3], qa2.x, B3);
            ffma2(acc[5][0], qa2.y, B0); ffma2(acc[5][1], qa2.y, B1);
            ffma2(acc[5][2], qa2.y, B2); ffma2(acc[5][3], qa2.y, B3);
            ffma2(acc[6][0], qa3.x, B0); ffma2(acc[6][1], qa3.x, B1);
            ffma2(acc[6][2], qa3.x, B2); ffma2(acc[6][3], qa3.x, B3);
            ffma2(acc[7][0], qa3.y, B0); ffma2(acc[7][1], qa3.y, B1);
            ffma2(acc[7][2], qa3.y, B2); ffma2(acc[7][3], qa3.y, B3);
        }
        if (kt + 1 < NT) {
            float* xn = xT + (buf ^ 1) * (BK1 * XTP);
            float v[8] = {xs0.x, xs0.y, xs0.z, xs0.w, xs1.x, xs1.y, xs1.z, xs1.w};
            #pragma unroll
            for (int i = 0; i < 8; ++i)
                xn[(xk + i) * XTP + xr] = v[i];
            if (buf) { mbar_wait(mb0, ph0); ph0 ^= 1; }
            else     { mbar_wait(mb1, ph1); ph1 ^= 1; }
        }
        __syncthreads();
    }

    // epilogue: +bias (dup-packed), per-pair sumsq butterfly, store P + g_sq
    float4 b4 = *(const float4*)(bias + nc);
    u64 bp[4];
    bp[0] = pack2(b4.x, b4.x); bp[1] = pack2(b4.y, b4.y);
    bp[2] = pack2(b4.z, b4.z); bp[3] = pack2(b4.w, b4.w);

    u64 sp[8];
    #pragma unroll
    for (int m = 0; m < 8; ++m) {
        sp[m] = 0ull;
        #pragma unroll
        for (int j = 0; j < 4; ++j) {
            fadd2(acc[m][j], bp[j]);
            ffma2(sp[m], acc[m][j], acc[m][j]);
        }
    }
    #pragma unroll
    for (int m = 0; m < 8; ++m)
        #pragma unroll
        for (int o = 16; o; o >>= 1) {
            u64 t = __shfl_xor_sync(0xffffffffu, sp[m], o);
            fadd2(sp[m], t);
        }

    #pragma unroll
    for (int m = 0; m < 8; ++m) {
        float lo[4], hi[4];
        #pragma unroll
        for (int j = 0; j < 4; ++j) unpack2(acc[m][j], lo[j], hi[j]);
        int r = t0 + mb + 2 * m;
        *(float4*)(g_P + (size_t)r * ED + nc)        = make_float4(lo[0], lo[1], lo[2], lo[3]);
        *(float4*)(g_P + (size_t)(r + 1) * ED + nc)  = make_float4(hi[0], hi[1], hi[2], hi[3]);
    }
    if (lane == 0) {
        #pragma unroll
        for (int m = 0; m < 8; ++m) {
            float se, so; unpack2(sp[m], se, so);
            sq_sm[mb + 2 * m][w >> 2]     = se;
            sq_sm[mb + 2 * m + 1][w >> 2] = so;
        }
    }
    __syncthreads();
    if (tid < 64) g_sq[t0 + tid] = sq_sm[tid][0] + sq_sm[tid][1];
}

// ---------------- K2: sims + top-2 + softmax (16 tokens x 128 experts/warp, smem merge) ----------------
#define C2BYTES (BK2 * NE * 4)
#define MGP 129     // mg pitch in float4 units

__global__ __launch_bounds__(256, 2)
void k2_kernel(float* __restrict__ out, int ntok) {
    extern __shared__ __align__(16) float sm2[];
    float* PsT = sm2;                      // [ED][PSTP] : P transposed [k][m]
    float* ct  = sm2 + ED * PSTP;          // [2][BK2][NE] center tiles
    __shared__ __align__(8) u64 mbars[2];

    const int tid = threadIdx.x;
    const int w = tid >> 5, lane = tid & 31;
    const int t0 = blockIdx.x * TT;
    const int g = w >> 2, h = w & 3;
    const int mb = g * 16;                 // 16 tokens per warp
    const int nc = h * 128 + lane * 4;     // 4 experts per lane within 128-expert group

    u32 ct_u32 = (u32)__cvta_generic_to_shared(ct);
    u32 mb0 = (u32)__cvta_generic_to_shared(&mbars[0]);
    u32 mb1 = mb0 + 8;
    int ph0 = 0, ph1 = 0;

    if (tid == 0) { mbar_init(mb0, 1); mbar_init(mb1, 1); }
    __syncthreads();
    if (tid == 0) { mbar_expect_tx(mb0, C2BYTES); bulk_g2s(ct_u32, g_cnT, C2BYTES, mb0); }

    // transpose P tile into PsT (overlaps with bulk copy)
    const int pr = tid >> 3, pcq = (tid & 7) * 4;
    #pragma unroll
    for (int j = 0; j < 8; ++j) {
        int c = pcq + 32 * j;
        float4 v = *(const float4*)(g_P + (size_t)(t0 + pr) * ED + c);
        PsT[(c + 0) * PSTP + pr] = v.x;
        PsT[(c + 1) * PSTP + pr] = v.y;
        PsT[(c + 2) * PSTP + pr] = v.z;
        PsT[(c + 3) * PSTP + pr] = v.w;
    }
    mbar_wait(mb0, ph0); ph0 ^= 1;
    __syncthreads();

    u64 acc[8][4];
    #pragma unroll
    for (int m = 0; m < 8; ++m)
        #pragma unroll
        for (int p = 0; p < 4; ++p) acc[m][p] = 0ull;

    const int NT = ED / BK2;
    for (int kt = 0; kt < NT; ++kt) {
        const int buf = kt & 1;
        const float* cb = ct + buf * (BK2 * NE);
        if (kt + 1 < NT && tid == 0) {
            u32 m = buf ? mb0 : mb1;
            mbar_expect_tx(m, C2BYTES);
            bulk_g2s(ct_u32 + (u32)((buf ^ 1) * C2BYTES),
                     g_cnT + (size_t)(kt + 1) * BK2 * NE, C2BYTES, m);
        }
        #pragma unroll
        for (int k = 0; k < BK2; ++k) {
            const int kk = kt * BK2 + k;
            const ulonglong2* ap = (const ulonglong2*)(PsT + kk * PSTP + mb);
            ulonglong2 qa0 = ap[0], qa1 = ap[1], qa2 = ap[2], qa3 = ap[3];
            float4 b = *(const float4*)(cb + k * NE + nc);
            u64 B0 = pack2(b.x, b.x), B1 = pack2(b.y, b.y);
            u64 B2 = pack2(b.z, b.z), B3 = pack2(b.w, b.w);
            ffma2(acc[0][0], qa0.x, B0); ffma2(acc[0][1], qa0.x, B1);
            ffma2(acc[0][2], qa0.x, B2); ffma2(acc[0][3], qa0.x, B3);
            ffma2(acc[1][0], qa0.y, B0); ffma2(acc[1][1], qa0.y, B1);
            ffma2(acc[1][2], qa0.y, B2); ffma2(acc[1][3], qa0.y, B3);
            ffma2(acc[2][0], qa1.x, B0); ffma2(acc[2][1], qa1.x, B1);
            ffma2(acc[2][2], qa1.x, B2); ffma2(acc[2][3], qa1.x, B3);
            ffma2(acc[3][0], qa1.y, B0); ffma2(acc[3][1], qa1.y, B1);
            ffma2(acc[3][2], qa1.y, B2); ffma2(acc[3][3], qa1.y, B3);
            ffma2(acc[4][0], qa2.x, B0); ffma2(acc[4][1], qa2.x, B1);
            ffma2(acc[4][2], qa2.x, B2); ffma2(acc[4][3], qa2.x, B3);
            ffma2(acc[5][0], qa2.y, B0); ffma2(acc[5][1], qa2.y, B1);
            ffma2(acc[5][2], qa2.y, B2); ffma2(acc[5][3], qa2.y, B3);
            ffma2(acc[6][0], qa3.x, B0); ffma2(acc[6][1], qa3.x, B1);
            ffma2(acc[6][2], qa3.x, B2); ffma2(acc[6][3], qa3.x, B3);
            ffma2(acc[7][0], qa3.y, B0); ffma2(acc[7][1], qa3.y, B1);
            ffma2(acc[7][2], qa3.y, B2); ffma2(acc[7][3], qa3.y, B3);
        }
        if (kt + 1 < NT) {
            if (buf) { mbar_wait(mb0, ph0); ph0 ^= 1; }
            else     { mbar_wait(mb1, ph1); ph1 ^= 1; }
        }
        __syncthreads();
    }

    // per-thread top-2 over this thread's 4 experts, per token slot
    float v1[16], v2[16]; int i1[16], i2[16];
    #pragma unroll
    for (int s = 0; s < 16; ++s) { v1[s] = -INFINITY; v2[s] = -INFINITY; i1[s] = 0; i2[s] = 0; }
    #pragma unroll
    for (int m = 0; m < 8; ++m)
        #pragma unroll
        for (int j = 0; j < 4; ++j) {
            float lo, hi; unpack2(acc[m][j], lo, hi);
            int gi = nc + j;
            upd(lo, gi, v1[2 * m],     i1[2 * m],     v2[2 * m],     i2[2 * m]);
            upd(hi, gi, v1[2 * m + 1], i1[2 * m + 1], v2[2 * m + 1], i2[2 * m + 1]);
        }

    // write per-lane top2 to mg (overlaid on ALL of sm2; PsT+ct dead after final sync above)
    float4* mg = (float4*)sm2;             // [TT][MGP] ; entry = h*32 + lane
    #pragma unroll
    for (int s = 0; s < 16; ++s)
        mg[(mb + s) * MGP + h * 32 + lane] =
            make_float4(v1[s], __int_as_float(i1[s]), v2[s], __int_as_float(i2[s]));
    __syncthreads();

    // merge: 128 threads, (token, quarter); scan 32 entries, then shfl merge over 4 quarters
    if (tid < 128) {
        const int token = tid >> 2, q = tid & 3;
        const float4* row = mg + token * MGP + q * 32;
        float4 E = row[0];
        float V1 = E.x, V2 = E.z;
        int I1 = __float_as_int(E.y), I2 = __float_as_int(E.w);
        #pragma unroll 8
        for (int e = 1; e < 32; ++e) {
            E = row[e];
            upd(E.x, __float_as_int(E.y), V1, I1, V2, I2);
            upd(E.z, __float_as_int(E.w), V1, I1, V2, I2);
        }
        #pragma unroll
        for (int off = 1; off <= 2; off <<= 1) {
            float o1 = __shfl_xor_sync(0xffffffffu, V1, off);
            int  oi1 = __shfl_xor_sync(0xffffffffu, I1, off);
            float o2 = __shfl_xor_sync(0xffffffffu, V2, off);
            int  oi2 = __shfl_xor_sync(0xffffffffu, I2, off);
            upd(o1, oi1, V1, I1, V2, I2);
            upd(o2, oi2, V1, I1, V2, I2);
        }
        if (q == 0) {
            int tok = t0 + token;
            float inv = 1.f / fmaxf(sqrtf(g_sq[tok]), 1e-12f);
            float e2 = expf((V2 - V1) * inv);
            float den = 1.f + e2;
            out[2 * tok]     = 1.f / den;
            out[2 * tok + 1] = e2 / den;
            float* oi = out + 2 * (size_t)ntok;
            oi[2 * tok]     = (float)I1;
            oi[2 * tok + 1] = (float)I2;
        }
    }
}

extern "C" void kernel_launch(void* const* d_in, const int* in_sizes, int n_in,
                              void* d_out, int out_size) {
    const float* x = (const float*)d_in[0];
    const float* W = (const float*)d_in[1];
    const float* b = (const float*)d_in[2];
    const float* c = (const float*)d_in[3];
    int ntok = in_sizes[0] / IN_DIM;   // 131072

    prep_kernel<<<NE + (IN_DIM / 32) * (ED / 32), 256>>>(c, W);

    int smem1 = (2 * BK1 * XTP + 2 * BK1 * ED) * (int)sizeof(float);   // 82944 B
    cudaFuncSetAttribute(k1_kernel, cudaFuncAttributeMaxDynamicSharedMemorySize, smem1);
    k1_kernel<<<ntok / 64, 256, smem1>>>(x, b);

    int smem2 = (ED * PSTP + 2 * BK2 * NE) * (int)sizeof(float);       // 102400 B
    cudaFuncSetAttribute(k2_kernel, cudaFuncAttributeMaxDynamicSharedMemorySize, smem2);
    k2_kernel<<<ntok / TT, 256, smem2>>>((float*)d_out, ntok);
}